// round 1
// baseline (speedup 1.0000x reference)
#include <cuda_runtime.h>

// HouseholderFlow fused kernel (baseline, fp32 f32x2 FMA path).
// Shapes: BATCH=16384, HIDDEN=1024, CODE=512, NUM_FLOW=8 (7 GEMM+HH layers).
// One CTA owns BM=32 rows and runs the entire flow in shared memory.

#define BM   32
#define CODE 512
#define HID  1024
#define TN   128      // n-chunk (output cols processed at once)
#define TK   32       // k-chunk
#define WTP  132      // wT row stride in floats (padded, even)
#define HSP  36       // hS row stride in floats (padded, mult of 4)
#define NTHREADS 256

typedef unsigned long long u64;

__device__ __forceinline__ u64 pack2(float x, float y) {
    u64 r; asm("mov.b64 %0, {%1,%2};" : "=l"(r) : "f"(x), "f"(y)); return r;
}
__device__ __forceinline__ u64 fma2(u64 a, u64 b, u64 c) {
    u64 d; asm("fma.rn.f32x2 %0, %1, %2, %3;" : "=l"(d) : "l"(a), "l"(b), "l"(c)); return d;
}

// Computes sOut[i][j] = bias[j] + sum_k A[i][k] * W[j][k]   for i in [0,32), j in [0,512)
// A comes either from gmem (layer 0, K=1024, rows m0..m0+31) or from smem (stride CODE).
// W is row-major [CODE][K]. Thread layout: tx = tid&15 (cols), ty = tid>>4 (rows ty, ty+16).
template<int K, bool FROM_GMEM>
__device__ __forceinline__ void gemm_layer(
    const float* __restrict__ gA, const float* __restrict__ sA,
    const float* __restrict__ W,  const float* __restrict__ bias,
    float* __restrict__ sOut, float* __restrict__ wT, float* __restrict__ hS,
    int m0, int tid)
{
    const int tx = tid & 15, ty = tid >> 4;
    const int arow = tid >> 3, akk = (tid & 7) * 4;   // A staging: 1 float4/thread
    const int jl = tid & 127, kb = (tid >> 7) * 4;    // W staging: 4 float4/thread

    for (int nc = 0; nc < CODE / TN; nc++) {
        u64 acc0[4], acc1[4];
        #pragma unroll
        for (int p = 0; p < 4; p++) {
            int c = nc * TN + 2 * tx + 32 * p;
            u64 bp = pack2(bias[c], bias[c + 1]);
            acc0[p] = bp; acc1[p] = bp;
        }

        for (int kc = 0; kc < K / TK; kc++) {
            // --- prefetch next tiles into registers (reads gA/sA only) ---
            float4 av;
            if (FROM_GMEM)
                av = *(const float4*)&gA[(size_t)(m0 + arow) * K + kc * TK + akk];
            else
                av = *(const float4*)&sA[arow * CODE + kc * TK + akk];
            float4 wv[4];
            #pragma unroll
            for (int it = 0; it < 4; it++) {
                int kkw = kb + 8 * it;
                wv[it] = *(const float4*)&W[(size_t)(nc * TN + jl) * K + kc * TK + kkw];
            }

            __syncthreads();   // previous compute done; safe to overwrite tiles
            *(float4*)&hS[arow * HSP + akk] = av;
            #pragma unroll
            for (int it = 0; it < 4; it++) {
                int kkw = kb + 8 * it;
                wT[(kkw + 0) * WTP + jl] = wv[it].x;
                wT[(kkw + 1) * WTP + jl] = wv[it].y;
                wT[(kkw + 2) * WTP + jl] = wv[it].z;
                wT[(kkw + 3) * WTP + jl] = wv[it].w;
            }
            __syncthreads();   // tiles ready

            #pragma unroll 8
            for (int k = 0; k < TK; k++) {
                float a0 = hS[ty * HSP + k];
                float a1 = hS[(ty + 16) * HSP + k];
                u64 va0 = pack2(a0, a0);
                u64 va1 = pack2(a1, a1);
                #pragma unroll
                for (int p = 0; p < 4; p++) {
                    u64 w2 = *(const u64*)&wT[k * WTP + 2 * tx + 32 * p];
                    acc0[p] = fma2(va0, w2, acc0[p]);
                    acc1[p] = fma2(va1, w2, acc1[p]);
                }
            }
        }

        #pragma unroll
        for (int p = 0; p < 4; p++) {
            int c = nc * TN + 2 * tx + 32 * p;
            *(u64*)&sOut[ty * CODE + c]        = acc0[p];
            *(u64*)&sOut[(ty + 16) * CODE + c] = acc1[p];
        }
    }
}

// z[i][:] -= 2 * v[i][:] * (v.z)/(v.v)  per row, in smem.
__device__ __forceinline__ void hh_update(const float* __restrict__ v,
                                          float* __restrict__ z, int tid)
{
    __syncthreads();   // v fully written
    const int warp = tid >> 5, lane = tid & 31;
    for (int r = warp; r < BM; r += 8) {
        float vz = 0.f, vv = 0.f;
        #pragma unroll
        for (int c = lane; c < CODE; c += 32) {
            float a = v[r * CODE + c];
            float b = z[r * CODE + c];
            vz += a * b;
            vv += a * a;
        }
        #pragma unroll
        for (int o = 16; o; o >>= 1) {
            vz += __shfl_xor_sync(0xffffffffu, vz, o);
            vv += __shfl_xor_sync(0xffffffffu, vv, o);
        }
        float s = 2.0f * vz / vv;
        #pragma unroll
        for (int c = lane; c < CODE; c += 32)
            z[r * CODE + c] -= s * v[r * CODE + c];
    }
    __syncthreads();   // z stable before next layer
}

// smem: vA[32][512] | vB[32][512] | zS[32][512] | wT[32][132] | hS[32][36]
#define SMEM_FLOATS (3 * BM * CODE + TK * WTP + BM * HSP)
#define SMEM_BYTES  (SMEM_FLOATS * 4)

extern __shared__ float smem[];

__global__ void __launch_bounds__(NTHREADS, 1)
hhflow_kernel(const float* __restrict__ hidden, const float* __restrict__ zs,
              const float* __restrict__ W0, const float* __restrict__ b0,
              const float* __restrict__ Ws, const float* __restrict__ bs,
              float* __restrict__ out)
{
    float* vA = smem;
    float* vB = vA + BM * CODE;
    float* zS = vB + BM * CODE;
    float* wT = zS + BM * CODE;
    float* hS = wT + TK * WTP;

    const int tid = threadIdx.x;
    const int m0  = blockIdx.x * BM;

    // load z block (rows m0..m0+31 are a contiguous BM*CODE slab)
    for (int i = tid; i < BM * CODE / 4; i += NTHREADS)
        *(float4*)&zS[i * 4] = *(const float4*)&zs[(size_t)m0 * CODE + i * 4];
    // no sync needed: zS is only read after hh_update's entry barrier

    // layer 0: v = hidden @ W0^T + b0
    gemm_layer<HID, true>(hidden, nullptr, W0, b0, vA, wT, hS, m0, tid);
    hh_update(vA, zS, tid);

    // layers 1..6: v = v @ Ws[l-1]^T + bs[l-1]
    #pragma unroll 1
    for (int l = 1; l <= 6; l++) {
        const float* Wl = Ws + (size_t)(l - 1) * CODE * CODE;
        const float* bl = bs + (size_t)(l - 1) * CODE;
        const float* src = (l & 1) ? vA : vB;
        float*       dst = (l & 1) ? vB : vA;
        gemm_layer<CODE, false>(nullptr, src, Wl, bl, dst, wT, hS, m0, tid);
        hh_update(dst, zS, tid);
    }

    // write final z
    for (int i = tid; i < BM * CODE / 4; i += NTHREADS)
        *(float4*)&out[(size_t)m0 * CODE + i * 4] = *(const float4*)&zS[i * 4];
}

extern "C" void kernel_launch(void* const* d_in, const int* in_sizes, int n_in,
                              void* d_out, int out_size)
{
    (void)in_sizes; (void)n_in; (void)out_size;
    const float* hidden = (const float*)d_in[0];
    const float* zs     = (const float*)d_in[1];
    const float* W0     = (const float*)d_in[2];
    const float* b0     = (const float*)d_in[3];
    const float* Ws     = (const float*)d_in[4];
    const float* bs     = (const float*)d_in[5];
    float* out = (float*)d_out;

    cudaFuncSetAttribute(hhflow_kernel,
                         cudaFuncAttributeMaxDynamicSharedMemorySize, SMEM_BYTES);
    hhflow_kernel<<<16384 / BM, NTHREADS, SMEM_BYTES>>>(hidden, zs, W0, b0, Ws, bs, out);
}

// round 3
// speedup vs baseline: 5.3913x; 5.3913x over previous
#include <cuda_runtime.h>
#include <cuda_bf16.h>
#include <cstdint>

#define BATCH 16384
#define CODE  512
#define HID   1024

// ---------------- static device scratch ----------------
__device__ __nv_bfloat16 g_Whi[CODE*HID + 6*CODE*CODE];
__device__ __nv_bfloat16 g_Wlo[CODE*HID + 6*CODE*CODE];
__device__ __nv_bfloat16 g_Hhi[BATCH*HID];
__device__ __nv_bfloat16 g_Hlo[BATCH*HID];
__device__ __nv_bfloat16 g_Vhi[2][BATCH*CODE];
__device__ __nv_bfloat16 g_Vlo[2][BATCH*CODE];

// ---------------- helpers ----------------
__device__ __forceinline__ uint32_t smem_u32(const void* p) {
    uint32_t a;
    asm("{ .reg .u64 t; cvta.to.shared.u64 t, %1; cvt.u32.u64 %0, t; }" : "=r"(a) : "l"(p));
    return a;
}
__device__ __forceinline__ void ldsm4(uint32_t* r, uint32_t a) {
    asm volatile("ldmatrix.sync.aligned.m8n8.x4.shared.b16 {%0,%1,%2,%3}, [%4];"
        : "=r"(r[0]), "=r"(r[1]), "=r"(r[2]), "=r"(r[3]) : "r"(a));
}
__device__ __forceinline__ void mma16816(float* d, const uint32_t* a, uint32_t b0, uint32_t b1) {
    asm volatile("mma.sync.aligned.m16n8k16.row.col.f32.bf16.bf16.f32 "
        "{%0,%1,%2,%3},{%4,%5,%6,%7},{%8,%9},{%0,%1,%2,%3};"
        : "+f"(d[0]), "+f"(d[1]), "+f"(d[2]), "+f"(d[3])
        : "r"(a[0]), "r"(a[1]), "r"(a[2]), "r"(a[3]), "r"(b0), "r"(b1));
}
#define CP_ASYNC(s, g) asm volatile("cp.async.cg.shared.global [%0], [%1], 16;" :: "r"(s), "l"(g))
#define CP_COMMIT()    asm volatile("cp.async.commit_group;")
#define CP_WAIT2()     asm volatile("cp.async.wait_group 2;")

__device__ __forceinline__ void store_hl(__nv_bfloat16* Vhi, __nv_bfloat16* Vlo,
                                         size_t off, float v0, float v1) {
    __nv_bfloat16 h0 = __float2bfloat16(v0), h1 = __float2bfloat16(v1);
    __nv_bfloat16 l0 = __float2bfloat16(v0 - __bfloat162float(h0));
    __nv_bfloat16 l1 = __float2bfloat16(v1 - __bfloat162float(h1));
    *(__nv_bfloat162*)(Vhi + off) = __halves2bfloat162(h0, h1);
    *(__nv_bfloat162*)(Vlo + off) = __halves2bfloat162(l0, l1);
}

// ---------------- fp32 -> bf16 hi/lo converter ----------------
__global__ void cvt_kernel(const float4* __restrict__ src,
                           __nv_bfloat162* __restrict__ hi,
                           __nv_bfloat162* __restrict__ lo, int n4) {
    int i = blockIdx.x * blockDim.x + threadIdx.x;
    if (i >= n4) return;
    float4 v = src[i];
    __nv_bfloat16 h0 = __float2bfloat16(v.x), h1 = __float2bfloat16(v.y);
    __nv_bfloat16 h2 = __float2bfloat16(v.z), h3 = __float2bfloat16(v.w);
    __nv_bfloat16 l0 = __float2bfloat16(v.x - __bfloat162float(h0));
    __nv_bfloat16 l1 = __float2bfloat16(v.y - __bfloat162float(h1));
    __nv_bfloat16 l2 = __float2bfloat16(v.z - __bfloat162float(h2));
    __nv_bfloat16 l3 = __float2bfloat16(v.w - __bfloat162float(h3));
    hi[2*i]   = __halves2bfloat162(h0, h1);
    hi[2*i+1] = __halves2bfloat162(h2, h3);
    lo[2*i]   = __halves2bfloat162(l0, l1);
    lo[2*i+1] = __halves2bfloat162(l2, l3);
}

// ---------------- GEMM: V = A @ W^T + bias, bf16 hi/lo 3-pass ----------------
// CTA tile 128x128, 8 warps of 64x32, 3-stage cp.async pipeline.
// Stage layout: A tile 128x64 bf16 (16KB) | B tile 128x64 bf16 (16KB)
#define STAGE_B  32768
#define GSMEM    (3 * STAGE_B)

template<int K>
__global__ void __launch_bounds__(256, 2)
gemm_layer(const __nv_bfloat16* __restrict__ Ahi, const __nv_bfloat16* __restrict__ Alo,
           const __nv_bfloat16* __restrict__ Bhi, const __nv_bfloat16* __restrict__ Blo,
           const float* __restrict__ bias,
           __nv_bfloat16* __restrict__ Vhi, __nv_bfloat16* __restrict__ Vlo)
{
    extern __shared__ char sm[];
    const uint32_t sb = smem_u32(sm);
    const int tid = threadIdx.x, lane = tid & 31, wid = tid >> 5;
    const int wm = wid & 1, wn = wid >> 1;            // 2 x 4 warp grid
    const int m0 = blockIdx.x * 128, n0 = blockIdx.y * 128;
    constexpr int KC64 = K / 64;
    constexpr int NITER = 3 * KC64;                   // hi*hi, hi*lo, lo*hi

    // ---- gmem->smem load offsets (per thread: 4 x 16B for A, 4 x 16B for B) ----
    const int lrow = tid >> 3, lc = tid & 7;
    uint32_t sOff[4], gAo[4], gBo[4];
    #pragma unroll
    for (int q = 0; q < 4; q++) {
        int row = lrow + q * 32;
        sOff[q] = (uint32_t)row * 128 + (uint32_t)((lc ^ (row & 7)) << 4);
        gAo[q] = (uint32_t)(m0 + row) * (K * 2) + lc * 16;
        gBo[q] = (uint32_t)(n0 + row) * (K * 2) + lc * 16;
    }

    // ---- ldmatrix source rows ----
    int rA[4];
    #pragma unroll
    for (int mt = 0; mt < 4; mt++) rA[mt] = wm * 64 + mt * 16 + (lane & 15);
    const int cA = lane >> 4;                             // 0/1 (k 16B-halves)
    int nB[2];
    #pragma unroll
    for (int p = 0; p < 2; p++) nB[p] = wn * 32 + p * 16 + (lane & 7) + ((lane >> 4) << 3);
    const int cB = (lane >> 3) & 1;

    float acc[16][4] = {};

    auto prefetch = [&](int it) {
        if (it < NITER) {
            const int pass = it / KC64, kc = it - pass * KC64;
            const char* As = (const char*)((pass == 2) ? Alo : Ahi);
            const char* Bs = (const char*)((pass == 1) ? Blo : Bhi);
            const uint32_t slot = sb + (uint32_t)(it % 3) * STAGE_B;
            #pragma unroll
            for (int q = 0; q < 4; q++)
                CP_ASYNC(slot + sOff[q], As + gAo[q] + kc * 128);
            #pragma unroll
            for (int q = 0; q < 4; q++)
                CP_ASYNC(slot + 16384 + sOff[q], Bs + gBo[q] + kc * 128);
        }
        CP_COMMIT();
    };

    prefetch(0);
    prefetch(1);

    for (int it = 0; it < NITER; it++) {
        __syncthreads();               // all warps done with slot (it+2)%3's old data
        prefetch(it + 2);
        CP_WAIT2();                    // group `it` complete (this thread)
        __syncthreads();               // stage `it` visible to all

        const uint32_t slot = sb + (uint32_t)(it % 3) * STAGE_B;
        #pragma unroll
        for (int ks = 0; ks < 4; ks++) {
            uint32_t a[4][4], b[2][4];
            #pragma unroll
            for (int mt = 0; mt < 4; mt++)
                ldsm4(a[mt], slot + (uint32_t)rA[mt] * 128 +
                      (uint32_t)((((ks * 2 + cA) ^ (rA[mt] & 7))) << 4));
            #pragma unroll
            for (int p = 0; p < 2; p++)
                ldsm4(b[p], slot + 16384 + (uint32_t)nB[p] * 128 +
                      (uint32_t)((((ks * 2 + cB) ^ (nB[p] & 7))) << 4));
            #pragma unroll
            for (int mt = 0; mt < 4; mt++)
                #pragma unroll
                for (int nt = 0; nt < 4; nt++)
                    mma16816(acc[mt * 4 + nt], a[mt],
                             b[nt >> 1][(nt & 1) * 2], b[nt >> 1][(nt & 1) * 2 + 1]);
        }
    }

    // ---- epilogue: +bias, write v as bf16 hi/lo ----
    const int gid = lane >> 2, qid = lane & 3;
    #pragma unroll
    for (int mt = 0; mt < 4; mt++) {
        #pragma unroll
        for (int nt = 0; nt < 4; nt++) {
            const float* d = acc[mt * 4 + nt];
            const int row = m0 + wm * 64 + mt * 16 + gid;
            const int col = n0 + wn * 32 + nt * 8 + qid * 2;
            const float b0 = __ldg(bias + col), b1 = __ldg(bias + col + 1);
            store_hl(Vhi, Vlo, (size_t)row * CODE + col,       d[0] + b0, d[1] + b1);
            store_hl(Vhi, Vlo, (size_t)(row + 8) * CODE + col, d[2] + b0, d[3] + b1);
        }
    }
}

// ---------------- Householder: z -= 2 v (v.z)/(v.v), one warp per row ----------------
__global__ void __launch_bounds__(256)
hh_kernel(const __nv_bfloat16* __restrict__ Vhi, const __nv_bfloat16* __restrict__ Vlo,
          const float* __restrict__ z_in, float* __restrict__ z_out)
{
    const int lane = threadIdx.x & 31, warp = threadIdx.x >> 5;
    const size_t row = (size_t)blockIdx.x * 8 + warp;
    const __nv_bfloat16* vh = Vhi + row * CODE;
    const __nv_bfloat16* vl = Vlo + row * CODE;
    const float* zi = z_in + row * CODE;

    float v[16], z[16];
    float vz = 0.f, vv = 0.f;
    #pragma unroll
    for (int ch = 0; ch < 4; ch++) {
        const int c = ch * 128 + lane * 4;
        uint2 hp = *(const uint2*)(vh + c);
        uint2 lp = *(const uint2*)(vl + c);
        float4 zt = *(const float4*)(zi + c);
        float2 h0 = __bfloat1622float2(*(const __nv_bfloat162*)&hp.x);
        float2 h1 = __bfloat1622float2(*(const __nv_bfloat162*)&hp.y);
        float2 l0 = __bfloat1622float2(*(const __nv_bfloat162*)&lp.x);
        float2 l1 = __bfloat1622float2(*(const __nv_bfloat162*)&lp.y);
        v[ch*4+0] = h0.x + l0.x; v[ch*4+1] = h0.y + l0.y;
        v[ch*4+2] = h1.x + l1.x; v[ch*4+3] = h1.y + l1.y;
        z[ch*4+0] = zt.x; z[ch*4+1] = zt.y; z[ch*4+2] = zt.z; z[ch*4+3] = zt.w;
        #pragma unroll
        for (int j = 0; j < 4; j++) {
            vz += v[ch*4+j] * z[ch*4+j];
            vv += v[ch*4+j] * v[ch*4+j];
        }
    }
    #pragma unroll
    for (int o = 16; o; o >>= 1) {
        vz += __shfl_xor_sync(0xffffffffu, vz, o);
        vv += __shfl_xor_sync(0xffffffffu, vv, o);
    }
    const float s = 2.f * vz / vv;
    float* zo = z_out + row * CODE;
    #pragma unroll
    for (int ch = 0; ch < 4; ch++) {
        const int c = ch * 128 + lane * 4;
        float4 o;
        o.x = z[ch*4+0] - s * v[ch*4+0];
        o.y = z[ch*4+1] - s * v[ch*4+1];
        o.z = z[ch*4+2] - s * v[ch*4+2];
        o.w = z[ch*4+3] - s * v[ch*4+3];
        *(float4*)(zo + c) = o;
    }
}

// ---------------- host launch ----------------
extern "C" void kernel_launch(void* const* d_in, const int* in_sizes, int n_in,
                              void* d_out, int out_size)
{
    (void)in_sizes; (void)n_in; (void)out_size;
    const float* hidden = (const float*)d_in[0];
    const float* zs     = (const float*)d_in[1];
    const float* W0     = (const float*)d_in[2];
    const float* b0     = (const float*)d_in[3];
    const float* Ws     = (const float*)d_in[4];
    const float* bs     = (const float*)d_in[5];
    float* out = (float*)d_out;

    void *pWhi, *pWlo, *pHhi, *pHlo, *pVhi, *pVlo;
    cudaGetSymbolAddress(&pWhi, g_Whi);
    cudaGetSymbolAddress(&pWlo, g_Wlo);
    cudaGetSymbolAddress(&pHhi, g_Hhi);
    cudaGetSymbolAddress(&pHlo, g_Hlo);
    cudaGetSymbolAddress(&pVhi, g_Vhi);
    cudaGetSymbolAddress(&pVlo, g_Vlo);
    __nv_bfloat16* Whi = (__nv_bfloat16*)pWhi;
    __nv_bfloat16* Wlo = (__nv_bfloat16*)pWlo;
    __nv_bfloat16* Hhi = (__nv_bfloat16*)pHhi;
    __nv_bfloat16* Hlo = (__nv_bfloat16*)pHlo;
    __nv_bfloat16* Vhi0 = (__nv_bfloat16*)pVhi;
    __nv_bfloat16* Vlo0 = (__nv_bfloat16*)pVlo;
    __nv_bfloat16* Vhi1 = Vhi0 + (size_t)BATCH * CODE;
    __nv_bfloat16* Vlo1 = Vlo0 + (size_t)BATCH * CODE;

    cudaFuncSetAttribute(gemm_layer<HID>,  cudaFuncAttributeMaxDynamicSharedMemorySize, GSMEM);
    cudaFuncSetAttribute(gemm_layer<CODE>, cudaFuncAttributeMaxDynamicSharedMemorySize, GSMEM);

    // converts
    const int nW0 = CODE * HID, nWs = 6 * CODE * CODE, nH = BATCH * HID;
    cvt_kernel<<<(nW0/4 + 255)/256, 256>>>((const float4*)W0, (__nv_bfloat162*)Whi,
                                           (__nv_bfloat162*)Wlo, nW0/4);
    cvt_kernel<<<(nWs/4 + 255)/256, 256>>>((const float4*)Ws, (__nv_bfloat162*)(Whi + nW0),
                                           (__nv_bfloat162*)(Wlo + nW0), nWs/4);
    cvt_kernel<<<(nH/4 + 255)/256, 256>>>((const float4*)hidden, (__nv_bfloat162*)Hhi,
                                          (__nv_bfloat162*)Hlo, nH/4);

    const dim3 ggrid(BATCH / 128, CODE / 128);   // 128 x 4
    const int hgrid = BATCH / 8;                 // 2048

    // layer 0
    gemm_layer<HID><<<ggrid, 256, GSMEM>>>(Hhi, Hlo, Whi, Wlo, b0, Vhi0, Vlo0);
    hh_kernel<<<hgrid, 256>>>(Vhi0, Vlo0, zs, out);

    // layers 1..6
    __nv_bfloat16 *curHi = Vhi0, *curLo = Vlo0, *nxtHi = Vhi1, *nxtLo = Vlo1;
    for (int l = 1; l <= 6; l++) {
        const __nv_bfloat16* Bh = Whi + nW0 + (size_t)(l - 1) * CODE * CODE;
        const __nv_bfloat16* Bl = Wlo + nW0 + (size_t)(l - 1) * CODE * CODE;
        gemm_layer<CODE><<<ggrid, 256, GSMEM>>>(curHi, curLo, Bh, Bl,
                                                bs + (l - 1) * CODE, nxtHi, nxtLo);
        hh_kernel<<<hgrid, 256>>>(nxtHi, nxtLo, out, out);
        __nv_bfloat16* t;
        t = curHi; curHi = nxtHi; nxtHi = t;
        t = curLo; curLo = nxtLo; nxtLo = t;
    }
}

// round 4
// speedup vs baseline: 5.8324x; 1.0818x over previous
#include <cuda_runtime.h>
#include <cuda_bf16.h>
#include <cstdint>

#define BATCH 16384
#define CODE  512
#define HID   1024

// ---------------- static device scratch ----------------
__device__ __nv_bfloat16 g_Whi[CODE*HID + 6*CODE*CODE];
__device__ __nv_bfloat16 g_Wlo[CODE*HID + 6*CODE*CODE];
__device__ __nv_bfloat16 g_Hhi[BATCH*HID];
__device__ __nv_bfloat16 g_Hlo[BATCH*HID];
__device__ __nv_bfloat16 g_Vhi[2][BATCH*CODE];
__device__ __nv_bfloat16 g_Vlo[2][BATCH*CODE];

// ---------------- helpers ----------------
__device__ __forceinline__ uint32_t smem_u32(const void* p) {
    uint32_t a;
    asm("{ .reg .u64 t; cvta.to.shared.u64 t, %1; cvt.u32.u64 %0, t; }" : "=r"(a) : "l"(p));
    return a;
}
__device__ __forceinline__ void ldsm4(uint32_t* r, uint32_t a) {
    asm volatile("ldmatrix.sync.aligned.m8n8.x4.shared.b16 {%0,%1,%2,%3}, [%4];"
        : "=r"(r[0]), "=r"(r[1]), "=r"(r[2]), "=r"(r[3]) : "r"(a));
}
__device__ __forceinline__ void mma16816(float* d, const uint32_t* a, uint32_t b0, uint32_t b1) {
    asm volatile("mma.sync.aligned.m16n8k16.row.col.f32.bf16.bf16.f32 "
        "{%0,%1,%2,%3},{%4,%5,%6,%7},{%8,%9},{%0,%1,%2,%3};"
        : "+f"(d[0]), "+f"(d[1]), "+f"(d[2]), "+f"(d[3])
        : "r"(a[0]), "r"(a[1]), "r"(a[2]), "r"(a[3]), "r"(b0), "r"(b1));
}
#define CP_ASYNC(s, g) asm volatile("cp.async.cg.shared.global [%0], [%1], 16;" :: "r"(s), "l"(g))
#define CP_COMMIT()    asm volatile("cp.async.commit_group;")
#define CP_WAIT2()     asm volatile("cp.async.wait_group 2;")

__device__ __forceinline__ void store_hl(__nv_bfloat16* Vhi, __nv_bfloat16* Vlo,
                                         size_t off, float v0, float v1) {
    __nv_bfloat16 h0 = __float2bfloat16(v0), h1 = __float2bfloat16(v1);
    __nv_bfloat16 l0 = __float2bfloat16(v0 - __bfloat162float(h0));
    __nv_bfloat16 l1 = __float2bfloat16(v1 - __bfloat162float(h1));
    *(__nv_bfloat162*)(Vhi + off) = __halves2bfloat162(h0, h1);
    *(__nv_bfloat162*)(Vlo + off) = __halves2bfloat162(l0, l1);
}

// ---------------- fp32 -> bf16 hi/lo converter ----------------
__global__ void cvt_kernel(const float4* __restrict__ src,
                           __nv_bfloat162* __restrict__ hi,
                           __nv_bfloat162* __restrict__ lo, int n4) {
    int i = blockIdx.x * blockDim.x + threadIdx.x;
    if (i >= n4) return;
    float4 v = src[i];
    __nv_bfloat16 h0 = __float2bfloat16(v.x), h1 = __float2bfloat16(v.y);
    __nv_bfloat16 h2 = __float2bfloat16(v.z), h3 = __float2bfloat16(v.w);
    __nv_bfloat16 l0 = __float2bfloat16(v.x - __bfloat162float(h0));
    __nv_bfloat16 l1 = __float2bfloat16(v.y - __bfloat162float(h1));
    __nv_bfloat16 l2 = __float2bfloat16(v.z - __bfloat162float(h2));
    __nv_bfloat16 l3 = __float2bfloat16(v.w - __bfloat162float(h3));
    hi[2*i]   = __halves2bfloat162(h0, h1);
    hi[2*i+1] = __halves2bfloat162(h2, h3);
    lo[2*i]   = __halves2bfloat162(l0, l1);
    lo[2*i+1] = __halves2bfloat162(l2, l3);
}

// ---------------- GEMM: V = A @ W^T + bias, fused 3-pass hi/lo ----------------
// CTA tile 128x128, 8 warps of 64x32, 3-stage cp.async pipeline.
// Each stage holds Ahi|Alo|Bhi|Blo (4 x 16KB = 64KB); each k-chunk is loaded
// once and reused for all 3 numeric passes (hi*hi + hi*lo + lo*hi) from regs.
#define SEC_B    16384
#define STAGE_B  (4 * SEC_B)           // 65536
#define GSMEM    (3 * STAGE_B)         // 196608

template<int K>
__global__ void __launch_bounds__(256, 1)
gemm_layer(const __nv_bfloat16* __restrict__ Ahi, const __nv_bfloat16* __restrict__ Alo,
           const __nv_bfloat16* __restrict__ Bhi, const __nv_bfloat16* __restrict__ Blo,
           const float* __restrict__ bias,
           __nv_bfloat16* __restrict__ Vhi, __nv_bfloat16* __restrict__ Vlo)
{
    extern __shared__ char sm[];
    const uint32_t sb = smem_u32(sm);
    const int tid = threadIdx.x, lane = tid & 31, wid = tid >> 5;
    const int wm = wid & 1, wn = wid >> 1;            // 2 x 4 warp grid
    const int m0 = blockIdx.x * 128, n0 = blockIdx.y * 128;
    constexpr int NITER = K / 64;

    // ---- gmem->smem load offsets (per thread: 4 x 16B per section) ----
    const int lrow = tid >> 3, lc = tid & 7;
    uint32_t sOff[4], gAo[4], gBo[4];
    #pragma unroll
    for (int q = 0; q < 4; q++) {
        int row = lrow + q * 32;
        sOff[q] = (uint32_t)row * 128 + (uint32_t)((lc ^ (row & 7)) << 4);
        gAo[q] = (uint32_t)(m0 + row) * (K * 2) + lc * 16;
        gBo[q] = (uint32_t)(n0 + row) * (K * 2) + lc * 16;
    }

    // ---- ldmatrix source rows ----
    int rA[4];
    #pragma unroll
    for (int mt = 0; mt < 4; mt++) rA[mt] = wm * 64 + mt * 16 + (lane & 15);
    const int cA = lane >> 4;
    int nB[2];
    #pragma unroll
    for (int p = 0; p < 2; p++) nB[p] = wn * 32 + p * 16 + (lane & 7) + ((lane >> 4) << 3);
    const int cB = (lane >> 3) & 1;

    float acc[16][4] = {};

    auto prefetch = [&](int it) {
        if (it < NITER) {
            const uint32_t slot = sb + (uint32_t)(it % 3) * STAGE_B;
            const uint32_t koff = (uint32_t)it * 128;
            #pragma unroll
            for (int q = 0; q < 4; q++) {
                CP_ASYNC(slot + 0*SEC_B + sOff[q], (const char*)Ahi + gAo[q] + koff);
                CP_ASYNC(slot + 1*SEC_B + sOff[q], (const char*)Alo + gAo[q] + koff);
                CP_ASYNC(slot + 2*SEC_B + sOff[q], (const char*)Bhi + gBo[q] + koff);
                CP_ASYNC(slot + 3*SEC_B + sOff[q], (const char*)Blo + gBo[q] + koff);
            }
        }
        CP_COMMIT();
    };

    prefetch(0);
    prefetch(1);

    for (int it = 0; it < NITER; it++) {
        __syncthreads();               // all warps done with slot (it+2)%3's old data
        prefetch(it + 2);
        CP_WAIT2();                    // stage `it` landed (this thread)
        __syncthreads();               // stage `it` visible to all

        const uint32_t slot = sb + (uint32_t)(it % 3) * STAGE_B;
        #pragma unroll
        for (int ks = 0; ks < 4; ks++) {
            uint32_t ah[4][4], al[4][4], bh[2][4], bl[2][4];
            #pragma unroll
            for (int mt = 0; mt < 4; mt++) {
                const uint32_t ro = (uint32_t)rA[mt] * 128 +
                    (uint32_t)((((ks * 2 + cA) ^ (rA[mt] & 7))) << 4);
                ldsm4(ah[mt], slot + 0*SEC_B + ro);
                ldsm4(al[mt], slot + 1*SEC_B + ro);
            }
            #pragma unroll
            for (int p = 0; p < 2; p++) {
                const uint32_t ro = (uint32_t)nB[p] * 128 +
                    (uint32_t)((((ks * 2 + cB) ^ (nB[p] & 7))) << 4);
                ldsm4(bh[p], slot + 2*SEC_B + ro);
                ldsm4(bl[p], slot + 3*SEC_B + ro);
            }
            #pragma unroll
            for (int mt = 0; mt < 4; mt++) {
                #pragma unroll
                for (int nt = 0; nt < 4; nt++) {
                    float* d = acc[mt * 4 + nt];
                    const uint32_t bh0 = bh[nt >> 1][(nt & 1) * 2];
                    const uint32_t bh1 = bh[nt >> 1][(nt & 1) * 2 + 1];
                    const uint32_t bl0 = bl[nt >> 1][(nt & 1) * 2];
                    const uint32_t bl1 = bl[nt >> 1][(nt & 1) * 2 + 1];
                    mma16816(d, ah[mt], bh0, bh1);   // hi*hi
                    mma16816(d, ah[mt], bl0, bl1);   // hi*lo
                    mma16816(d, al[mt], bh0, bh1);   // lo*hi
                }
            }
        }
    }

    // ---- epilogue: +bias, write v as bf16 hi/lo ----
    const int gid = lane >> 2, qid = lane & 3;
    #pragma unroll
    for (int mt = 0; mt < 4; mt++) {
        #pragma unroll
        for (int nt = 0; nt < 4; nt++) {
            const float* d = acc[mt * 4 + nt];
            const int row = m0 + wm * 64 + mt * 16 + gid;
            const int col = n0 + wn * 32 + nt * 8 + qid * 2;
            const float b0 = __ldg(bias + col), b1 = __ldg(bias + col + 1);
            store_hl(Vhi, Vlo, (size_t)row * CODE + col,       d[0] + b0, d[1] + b1);
            store_hl(Vhi, Vlo, (size_t)(row + 8) * CODE + col, d[2] + b0, d[3] + b1);
        }
    }
}

// ---------------- Householder: z -= 2 v (v.z)/(v.v), one warp per row ----------------
__global__ void __launch_bounds__(256)
hh_kernel(const __nv_bfloat16* __restrict__ Vhi, const __nv_bfloat16* __restrict__ Vlo,
          const float* __restrict__ z_in, float* __restrict__ z_out)
{
    const int lane = threadIdx.x & 31, warp = threadIdx.x >> 5;
    const size_t row = (size_t)blockIdx.x * 8 + warp;
    const __nv_bfloat16* vh = Vhi + row * CODE;
    const __nv_bfloat16* vl = Vlo + row * CODE;
    const float* zi = z_in + row * CODE;

    float v[16], z[16];
    float vz = 0.f, vv = 0.f;
    #pragma unroll
    for (int ch = 0; ch < 4; ch++) {
        const int c = ch * 128 + lane * 4;
        uint2 hp = *(const uint2*)(vh + c);
        uint2 lp = *(const uint2*)(vl + c);
        float4 zt = *(const float4*)(zi + c);
        float2 h0 = __bfloat1622float2(*(const __nv_bfloat162*)&hp.x);
        float2 h1 = __bfloat1622float2(*(const __nv_bfloat162*)&hp.y);
        float2 l0 = __bfloat1622float2(*(const __nv_bfloat162*)&lp.x);
        float2 l1 = __bfloat1622float2(*(const __nv_bfloat162*)&lp.y);
        v[ch*4+0] = h0.x + l0.x; v[ch*4+1] = h0.y + l0.y;
        v[ch*4+2] = h1.x + l1.x; v[ch*4+3] = h1.y + l1.y;
        z[ch*4+0] = zt.x; z[ch*4+1] = zt.y; z[ch*4+2] = zt.z; z[ch*4+3] = zt.w;
        #pragma unroll
        for (int j = 0; j < 4; j++) {
            vz += v[ch*4+j] * z[ch*4+j];
            vv += v[ch*4+j] * v[ch*4+j];
        }
    }
    #pragma unroll
    for (int o = 16; o; o >>= 1) {
        vz += __shfl_xor_sync(0xffffffffu, vz, o);
        vv += __shfl_xor_sync(0xffffffffu, vv, o);
    }
    const float s = 2.f * vz / vv;
    float* zo = z_out + row * CODE;
    #pragma unroll
    for (int ch = 0; ch < 4; ch++) {
        const int c = ch * 128 + lane * 4;
        float4 o;
        o.x = z[ch*4+0] - s * v[ch*4+0];
        o.y = z[ch*4+1] - s * v[ch*4+1];
        o.z = z[ch*4+2] - s * v[ch*4+2];
        o.w = z[ch*4+3] - s * v[ch*4+3];
        *(float4*)(zo + c) = o;
    }
}

// ---------------- host launch ----------------
extern "C" void kernel_launch(void* const* d_in, const int* in_sizes, int n_in,
                              void* d_out, int out_size)
{
    (void)in_sizes; (void)n_in; (void)out_size;
    const float* hidden = (const float*)d_in[0];
    const float* zs     = (const float*)d_in[1];
    const float* W0     = (const float*)d_in[2];
    const float* b0     = (const float*)d_in[3];
    const float* Ws     = (const float*)d_in[4];
    const float* bs     = (const float*)d_in[5];
    float* out = (float*)d_out;

    void *pWhi, *pWlo, *pHhi, *pHlo, *pVhi, *pVlo;
    cudaGetSymbolAddress(&pWhi, g_Whi);
    cudaGetSymbolAddress(&pWlo, g_Wlo);
    cudaGetSymbolAddress(&pHhi, g_Hhi);
    cudaGetSymbolAddress(&pHlo, g_Hlo);
    cudaGetSymbolAddress(&pVhi, g_Vhi);
    cudaGetSymbolAddress(&pVlo, g_Vlo);
    __nv_bfloat16* Whi = (__nv_bfloat16*)pWhi;
    __nv_bfloat16* Wlo = (__nv_bfloat16*)pWlo;
    __nv_bfloat16* Hhi = (__nv_bfloat16*)pHhi;
    __nv_bfloat16* Hlo = (__nv_bfloat16*)pHlo;
    __nv_bfloat16* Vhi0 = (__nv_bfloat16*)pVhi;
    __nv_bfloat16* Vlo0 = (__nv_bfloat16*)pVlo;
    __nv_bfloat16* Vhi1 = Vhi0 + (size_t)BATCH * CODE;
    __nv_bfloat16* Vlo1 = Vlo0 + (size_t)BATCH * CODE;

    cudaFuncSetAttribute(gemm_layer<HID>,  cudaFuncAttributeMaxDynamicSharedMemorySize, GSMEM);
    cudaFuncSetAttribute(gemm_layer<CODE>, cudaFuncAttributeMaxDynamicSharedMemorySize, GSMEM);

    // converts
    const int nW0 = CODE * HID, nWs = 6 * CODE * CODE, nH = BATCH * HID;
    cvt_kernel<<<(nW0/4 + 255)/256, 256>>>((const float4*)W0, (__nv_bfloat162*)Whi,
                                           (__nv_bfloat162*)Wlo, nW0/4);
    cvt_kernel<<<(nWs/4 + 255)/256, 256>>>((const float4*)Ws, (__nv_bfloat162*)(Whi + nW0),
                                           (__nv_bfloat162*)(Wlo + nW0), nWs/4);
    cvt_kernel<<<(nH/4 + 255)/256, 256>>>((const float4*)hidden, (__nv_bfloat162*)Hhi,
                                          (__nv_bfloat162*)Hlo, nH/4);

    const dim3 ggrid(BATCH / 128, CODE / 128);   // 128 x 4
    const int hgrid = BATCH / 8;                 // 2048

    // layer 0
    gemm_layer<HID><<<ggrid, 256, GSMEM>>>(Hhi, Hlo, Whi, Wlo, b0, Vhi0, Vlo0);
    hh_kernel<<<hgrid, 256>>>(Vhi0, Vlo0, zs, out);

    // layers 1..6
    __nv_bfloat16 *curHi = Vhi0, *curLo = Vlo0, *nxtHi = Vhi1, *nxtLo = Vlo1;
    for (int l = 1; l <= 6; l++) {
        const __nv_bfloat16* Bh = Whi + nW0 + (size_t)(l - 1) * CODE * CODE;
        const __nv_bfloat16* Bl = Wlo + nW0 + (size_t)(l - 1) * CODE * CODE;
        gemm_layer<CODE><<<ggrid, 256, GSMEM>>>(curHi, curLo, Bh, Bl,
                                                bs + (l - 1) * CODE, nxtHi, nxtLo);
        hh_kernel<<<hgrid, 256>>>(nxtHi, nxtLo, out, out);
        __nv_bfloat16* t;
        t = curHi; curHi = nxtHi; nxtHi = t;
        t = curLo; curLo = nxtLo; nxtLo = t;
    }
}